// round 6
// baseline (speedup 1.0000x reference)
#include <cuda_runtime.h>
#include <cstdint>

// Depthwise 3x3 conv, stride 1, VALID, C=64.
// x: (16, 64, 512, 512) f32, w: (64, 3, 3) f32 -> out: (16, 64, 510, 510) f32
//
// HBM-roofline kernel (~2.13 GB compulsory traffic). Inner loop is the
// proven-best R1 structure (328us, DRAM=84.5%): no smem, no shfl, each
// thread owns 4 output columns, rolling 3-row register window, TILE_H=10,
// packed fma.rn.f32x2, STG.64 stores, regs=32 @ 16 blocks/SM.
// R6 change: PERSISTENT blocks. One wave (152 SMs x 16 blocks = 2432),
// grid-stride over all 52224 (tile, c, n) work items. Eliminates the 21
// wave transitions + per-block cold-start latency ramps that account for
// the measured 15% DRAM idle.

#define TILE_H 10    // 510 = 51 * 10
#define THREADS 128  // 128 threads * 4 cols = 512 >= 510
#define NTILES  51
#define NCHAN   64
#define NBATCH  16
#define TOTAL_ITEMS (NTILES * NCHAN * NBATCH)  // 52224
#define PERSIST_BLOCKS 2432                    // 152 SMs * 16 blocks

typedef unsigned long long u64;

__device__ __forceinline__ u64 fpack2(float lo, float hi) {
    u64 d;
    asm("mov.b64 %0, {%1, %2};" : "=l"(d) : "f"(lo), "f"(hi));
    return d;
}

__device__ __forceinline__ u64 fmul2(u64 a, u64 b) {
    u64 d;
    asm("mul.rn.f32x2 %0, %1, %2;" : "=l"(d) : "l"(a), "l"(b));
    return d;
}

__device__ __forceinline__ u64 ffma2(u64 a, u64 b, u64 c) {
    u64 d;
    asm("fma.rn.f32x2 %0, %1, %2, %3;" : "=l"(d) : "l"(a), "l"(b), "l"(c));
    return d;
}

// Load 6 consecutive floats at p (16B aligned) -> 5 overlapping f32x2 pairs.
// `last` thread (cols 508..511): cols 512/513 may be OOB at the image end;
// zero them (they only feed the two invalid outputs 510/511).
__device__ __forceinline__ void load_row_pairs(const float* __restrict__ p,
                                               bool last, u64 q[5]) {
    float4 a = *reinterpret_cast<const float4*>(p);
    float v4 = 0.0f, v5 = 0.0f;
    if (!last) {
        float2 b = *reinterpret_cast<const float2*>(p + 4);
        v4 = b.x;
        v5 = b.y;
    }
    q[0] = fpack2(a.x, a.y);
    q[1] = fpack2(a.y, a.z);
    q[2] = fpack2(a.z, a.w);
    q[3] = fpack2(a.w, v4);
    q[4] = fpack2(v4, v5);
}

__global__ void __launch_bounds__(THREADS, 16)
dwconv3x3_kernel(const float* __restrict__ x,
                 const float* __restrict__ w,
                 float* __restrict__ out) {
    const int tid = threadIdx.x;
    const int x0  = tid * 4;               // first owned output column
    const bool last = (x0 == 508);         // thread 127: 2 valid outputs only

    for (int t = blockIdx.x; t < TOTAL_ITEMS; t += PERSIST_BLOCKS) {
        // Decompose work item: t = ((n * NCHAN) + c) * NTILES + tile
        const int img_id = t / NTILES;      // n * 64 + c
        const int tile   = t - img_id * NTILES;
        const int c      = img_id & (NCHAN - 1);

        const float* img = x + (size_t)img_id * (512 * 512);
        float* o = out + (size_t)img_id * (510 * 510);

        const int r0 = tile * TILE_H;      // first output row of this tile

        // Broadcast weights as (w,w) f32x2 pairs (L1/L2-resident, tiny).
        const float* wc = w + c * 9;
        u64 wp[9];
#pragma unroll
        for (int i = 0; i < 9; ++i) {
            float wv = __ldg(wc + i);
            wp[i] = fpack2(wv, wv);
        }

        // Rolling 3-row window of overlapping pairs.
        u64 q[3][5];
        load_row_pairs(img + (size_t)(r0 + 0) * 512 + x0, last, q[0]);
        load_row_pairs(img + (size_t)(r0 + 1) * 512 + x0, last, q[1]);

#pragma unroll
        for (int r = 0; r < TILE_H; ++r) {
            const int top = r % 3;
            const int mid = (r + 1) % 3;
            const int bot = (r + 2) % 3;

            load_row_pairs(img + (size_t)(r0 + r + 2) * 512 + x0, last, q[bot]);

            // outputs (x0, x0+1)
            u64 acc01 = fmul2(wp[0], q[top][0]);
            acc01 = ffma2(wp[1], q[top][1], acc01);
            acc01 = ffma2(wp[2], q[top][2], acc01);
            acc01 = ffma2(wp[3], q[mid][0], acc01);
            acc01 = ffma2(wp[4], q[mid][1], acc01);
            acc01 = ffma2(wp[5], q[mid][2], acc01);
            acc01 = ffma2(wp[6], q[bot][0], acc01);
            acc01 = ffma2(wp[7], q[bot][1], acc01);
            acc01 = ffma2(wp[8], q[bot][2], acc01);

            // outputs (x0+2, x0+3)
            u64 acc23 = fmul2(wp[0], q[top][2]);
            acc23 = ffma2(wp[1], q[top][3], acc23);
            acc23 = ffma2(wp[2], q[top][4], acc23);
            acc23 = ffma2(wp[3], q[mid][2], acc23);
            acc23 = ffma2(wp[4], q[mid][3], acc23);
            acc23 = ffma2(wp[5], q[mid][4], acc23);
            acc23 = ffma2(wp[6], q[bot][2], acc23);
            acc23 = ffma2(wp[7], q[bot][3], acc23);
            acc23 = ffma2(wp[8], q[bot][4], acc23);

            // Row stride 510*4 = 2040 B is 8-byte aligned -> STG.64 stores.
            float* orow = o + (size_t)(r0 + r) * 510 + x0;
            *reinterpret_cast<u64*>(orow) = acc01;
            if (!last) {
                *reinterpret_cast<u64*>(orow + 2) = acc23;
            }
        }
    }
}

extern "C" void kernel_launch(void* const* d_in, const int* in_sizes, int n_in,
                              void* d_out, int out_size) {
    const float* x = (const float*)d_in[0];
    const float* w = (const float*)d_in[1];
    // Defensive: metadata order is (x, weight); swap if sizes say otherwise.
    if (n_in >= 2 && in_sizes[0] < in_sizes[1]) {
        const float* t = x; x = w; w = t;
    }
    float* out = (float*)d_out;

    dwconv3x3_kernel<<<PERSIST_BLOCKS, THREADS>>>(x, w, out);
}

// round 7
// speedup vs baseline: 1.1019x; 1.1019x over previous
#include <cuda_runtime.h>
#include <cstdint>

// Depthwise 3x3 conv, stride 1, VALID, C=64.
// x: (16, 64, 512, 512) f32, w: (64, 3, 3) f32 -> out: (16, 64, 510, 510) f32
//
// HBM-roofline kernel (~2.14 GB compulsory traffic). Inner loop is the
// proven-best R1 structure (328us, DRAM=84.5%): no smem, no shfl, each
// thread owns 4 output columns, rolling 3-row register window, packed
// fma.rn.f32x2, STG.64 stores, regs=32.
// R7 change: TILE_H 10 -> 6. More frequent block prologues (2 dependency-free
// row loads each) raise the average outstanding-load depth (MLP_eff), which
// is the binding resource. Extra halo (1.33x vs 1.2x) is L2-absorbed
// (measured: DRAM bytes == compulsory floor, L2 has headroom).

#define TILE_H 6    // 510 = 85 * 6
#define THREADS 128 // 128 threads * 4 cols = 512 >= 510

typedef unsigned long long u64;

__device__ __forceinline__ u64 fpack2(float lo, float hi) {
    u64 d;
    asm("mov.b64 %0, {%1, %2};" : "=l"(d) : "f"(lo), "f"(hi));
    return d;
}

__device__ __forceinline__ u64 fmul2(u64 a, u64 b) {
    u64 d;
    asm("mul.rn.f32x2 %0, %1, %2;" : "=l"(d) : "l"(a), "l"(b));
    return d;
}

__device__ __forceinline__ u64 ffma2(u64 a, u64 b, u64 c) {
    u64 d;
    asm("fma.rn.f32x2 %0, %1, %2, %3;" : "=l"(d) : "l"(a), "l"(b), "l"(c));
    return d;
}

// Load 6 consecutive floats at p (16B aligned) -> 5 overlapping f32x2 pairs.
// `last` thread (cols 508..511): cols 512/513 may be OOB at the image end;
// zero them (they only feed the two invalid outputs 510/511).
__device__ __forceinline__ void load_row_pairs(const float* __restrict__ p,
                                               bool last, u64 q[5]) {
    float4 a = *reinterpret_cast<const float4*>(p);
    float v4 = 0.0f, v5 = 0.0f;
    if (!last) {
        float2 b = *reinterpret_cast<const float2*>(p + 4);
        v4 = b.x;
        v5 = b.y;
    }
    q[0] = fpack2(a.x, a.y);
    q[1] = fpack2(a.y, a.z);
    q[2] = fpack2(a.z, a.w);
    q[3] = fpack2(a.w, v4);
    q[4] = fpack2(v4, v5);
}

__global__ void __launch_bounds__(THREADS)
dwconv3x3_kernel(const float* __restrict__ x,
                 const float* __restrict__ w,
                 float* __restrict__ out) {
    const int tile = blockIdx.x;   // 0..84
    const int c    = blockIdx.y;   // 0..63
    const int n    = blockIdx.z;   // 0..15

    const int tid = threadIdx.x;
    const int x0  = tid * 4;               // first owned output column
    const bool last = (x0 == 508);         // thread 127: 2 valid outputs only

    const size_t img_off = ((size_t)(n * 64 + c)) * (512 * 512);
    const size_t out_off = ((size_t)(n * 64 + c)) * (510 * 510);
    const float* img = x + img_off;
    float* o = out + out_off;

    const int r0 = tile * TILE_H;          // first output row of this tile

    // Broadcast weights as (w,w) f32x2 pairs.
    const float* wc = w + c * 9;
    u64 wp[9];
#pragma unroll
    for (int i = 0; i < 9; ++i) {
        float wv = __ldg(wc + i);
        wp[i] = fpack2(wv, wv);
    }

    // Rolling 3-row window of overlapping pairs.
    u64 q[3][5];
    load_row_pairs(img + (size_t)(r0 + 0) * 512 + x0, last, q[0]);
    load_row_pairs(img + (size_t)(r0 + 1) * 512 + x0, last, q[1]);

#pragma unroll
    for (int r = 0; r < TILE_H; ++r) {
        const int top = r % 3;
        const int mid = (r + 1) % 3;
        const int bot = (r + 2) % 3;

        load_row_pairs(img + (size_t)(r0 + r + 2) * 512 + x0, last, q[bot]);

        // outputs (x0, x0+1)
        u64 acc01 = fmul2(wp[0], q[top][0]);
        acc01 = ffma2(wp[1], q[top][1], acc01);
        acc01 = ffma2(wp[2], q[top][2], acc01);
        acc01 = ffma2(wp[3], q[mid][0], acc01);
        acc01 = ffma2(wp[4], q[mid][1], acc01);
        acc01 = ffma2(wp[5], q[mid][2], acc01);
        acc01 = ffma2(wp[6], q[bot][0], acc01);
        acc01 = ffma2(wp[7], q[bot][1], acc01);
        acc01 = ffma2(wp[8], q[bot][2], acc01);

        // outputs (x0+2, x0+3)
        u64 acc23 = fmul2(wp[0], q[top][2]);
        acc23 = ffma2(wp[1], q[top][3], acc23);
        acc23 = ffma2(wp[2], q[top][4], acc23);
        acc23 = ffma2(wp[3], q[mid][2], acc23);
        acc23 = ffma2(wp[4], q[mid][3], acc23);
        acc23 = ffma2(wp[5], q[mid][4], acc23);
        acc23 = ffma2(wp[6], q[bot][2], acc23);
        acc23 = ffma2(wp[7], q[bot][3], acc23);
        acc23 = ffma2(wp[8], q[bot][4], acc23);

        // Row stride 510*4 = 2040 B is 8-byte aligned -> STG.64 stores.
        float* orow = o + (size_t)(r0 + r) * 510 + x0;
        *reinterpret_cast<u64*>(orow) = acc01;
        if (!last) {
            *reinterpret_cast<u64*>(orow + 2) = acc23;
        }
    }
}

extern "C" void kernel_launch(void* const* d_in, const int* in_sizes, int n_in,
                              void* d_out, int out_size) {
    const float* x = (const float*)d_in[0];
    const float* w = (const float*)d_in[1];
    // Defensive: metadata order is (x, weight); swap if sizes say otherwise.
    if (n_in >= 2 && in_sizes[0] < in_sizes[1]) {
        const float* t = x; x = w; w = t;
    }
    float* out = (float*)d_out;

    dim3 grid(85, 64, 16); // 510/TILE_H row tiles, C, N
    dwconv3x3_kernel<<<grid, THREADS>>>(x, w, out);
}

// round 8
// speedup vs baseline: 1.2059x; 1.0944x over previous
#include <cuda_runtime.h>
#include <cstdint>

// Depthwise 3x3 conv, stride 1, VALID, C=64.
// x: (16, 64, 512, 512) f32, w: (64, 3, 3) f32 -> out: (16, 64, 510, 510) f32
//
// R8: async-pipelined variant. The whole 12-row input tile is prefetched
// into shared memory with cp.async.cg (one commit-group per row, all issued
// at block start -> ~25KB outstanding per block, MLP decoupled from regs
// and occupancy). The compute loop is the proven R1 rolling-window FFMA2
// loop, consuming rows behind progressive cp.async.wait_group + barrier.
// Smem slots are 520 floats; cols 512/513 are zeroed once so all threads
// load uniformly (no edge branch on the load path).

#define TILE_H 10    // 510 = 51 * 10
#define ROWS_IN (TILE_H + 2)
#define THREADS 128  // 128 threads * 4 cols = 512
#define SLOT_F 520   // floats per smem row slot (512 data + 2 zero + pad)

typedef unsigned long long u64;

__device__ __forceinline__ u64 fpack2(float lo, float hi) {
    u64 d;
    asm("mov.b64 %0, {%1, %2};" : "=l"(d) : "f"(lo), "f"(hi));
    return d;
}

__device__ __forceinline__ u64 fmul2(u64 a, u64 b) {
    u64 d;
    asm("mul.rn.f32x2 %0, %1, %2;" : "=l"(d) : "l"(a), "l"(b));
    return d;
}

__device__ __forceinline__ u64 ffma2(u64 a, u64 b, u64 c) {
    u64 d;
    asm("fma.rn.f32x2 %0, %1, %2, %3;" : "=l"(d) : "l"(a), "l"(b), "l"(c));
    return d;
}

__device__ __forceinline__ void cp_async16(uint32_t smem_addr,
                                           const float* gptr) {
    asm volatile("cp.async.cg.shared.global [%0], [%1], 16;"
                 :: "r"(smem_addr), "l"(gptr));
}

__device__ __forceinline__ void cp_commit() {
    asm volatile("cp.async.commit_group;");
}

template <int N>
__device__ __forceinline__ void cp_wait() {
    asm volatile("cp.async.wait_group %0;" :: "n"(N));
}

// Progressive wait: rows 0..k+? — after this, >= (ROWS_IN - N) oldest
// groups (rows) have landed.
__device__ __forceinline__ void cp_wait_rt(int r) {
    // r is a compile-time constant in the unrolled loop; branches fold.
    if (r == 0) cp_wait<9>();
    else if (r == 1) cp_wait<8>();
    else if (r == 2) cp_wait<7>();
    else if (r == 3) cp_wait<6>();
    else if (r == 4) cp_wait<5>();
    else if (r == 5) cp_wait<4>();
    else if (r == 6) cp_wait<3>();
    else if (r == 7) cp_wait<2>();
    else if (r == 8) cp_wait<1>();
    else cp_wait<0>();
}

// Build 5 overlapping f32x2 pairs from a smem row slot (uniform; cols
// 512/513 hold zeros so thread 127 needs no branch).
__device__ __forceinline__ void pairs_from_smem(const float* srow, int x0,
                                                u64 q[5]) {
    float4 a = *reinterpret_cast<const float4*>(srow + x0);
    float2 b = *reinterpret_cast<const float2*>(srow + x0 + 4);
    q[0] = fpack2(a.x, a.y);
    q[1] = fpack2(a.y, a.z);
    q[2] = fpack2(a.z, a.w);
    q[3] = fpack2(a.w, b.x);
    q[4] = fpack2(b.x, b.y);
}

__global__ void __launch_bounds__(THREADS)
dwconv3x3_kernel(const float* __restrict__ x,
                 const float* __restrict__ w,
                 float* __restrict__ out) {
    __shared__ __align__(16) float sm[ROWS_IN * SLOT_F];

    const int tile = blockIdx.x;   // 0..50
    const int c    = blockIdx.y;   // 0..63
    const int n    = blockIdx.z;   // 0..15

    const int tid = threadIdx.x;
    const int x0  = tid * 4;               // first owned output column
    const bool last = (x0 == 508);         // thread 127: 2 valid outputs only

    const size_t img_off = ((size_t)(n * 64 + c)) * (512 * 512);
    const size_t out_off = ((size_t)(n * 64 + c)) * (510 * 510);
    const float* img = x + img_off;
    float* o = out + out_off;

    const int r0 = tile * TILE_H;          // first output row of this tile

    // Issue the whole tile's loads up front: one 16B cp.async per thread per
    // row, one commit-group per row. ~25KB in flight per block.
    const uint32_t smem_base =
        (uint32_t)__cvta_generic_to_shared(sm) + (uint32_t)(x0 * 4);
#pragma unroll
    for (int rr = 0; rr < ROWS_IN; ++rr) {
        cp_async16(smem_base + rr * (SLOT_F * 4),
                   img + (size_t)(r0 + rr) * 512 + x0);
        cp_commit();
    }

    // Zero the 2 halo floats of each slot (cols 512/513). Disjoint from the
    // cp.async target range, so no race.
    if (tid < ROWS_IN) {
        *reinterpret_cast<float2*>(sm + tid * SLOT_F + 512) =
            make_float2(0.0f, 0.0f);
    }

    // Broadcast weights as (w,w) f32x2 pairs.
    const float* wc = w + c * 9;
    u64 wp[9];
#pragma unroll
    for (int i = 0; i < 9; ++i) {
        float wv = __ldg(wc + i);
        wp[i] = fpack2(wv, wv);
    }

    // Rolling 3-row window of overlapping pairs.
    u64 q[3][5];
    cp_wait<ROWS_IN - 2>();   // rows 0,1 arrived (groups complete in order)
    __syncthreads();
    pairs_from_smem(sm + 0 * SLOT_F, x0, q[0]);
    pairs_from_smem(sm + 1 * SLOT_F, x0, q[1]);

#pragma unroll
    for (int r = 0; r < TILE_H; ++r) {
        const int top = r % 3;
        const int mid = (r + 1) % 3;
        const int bot = (r + 2) % 3;

        cp_wait_rt(r);        // row r+2 has landed
        __syncthreads();

        pairs_from_smem(sm + (r + 2) * SLOT_F, x0, q[bot]);

        // outputs (x0, x0+1)
        u64 acc01 = fmul2(wp[0], q[top][0]);
        acc01 = ffma2(wp[1], q[top][1], acc01);
        acc01 = ffma2(wp[2], q[top][2], acc01);
        acc01 = ffma2(wp[3], q[mid][0], acc01);
        acc01 = ffma2(wp[4], q[mid][1], acc01);
        acc01 = ffma2(wp[5], q[mid][2], acc01);
        acc01 = ffma2(wp[6], q[bot][0], acc01);
        acc01 = ffma2(wp[7], q[bot][1], acc01);
        acc01 = ffma2(wp[8], q[bot][2], acc01);

        // outputs (x0+2, x0+3)
        u64 acc23 = fmul2(wp[0], q[top][2]);
        acc23 = ffma2(wp[1], q[top][3], acc23);
        acc23 = ffma2(wp[2], q[top][4], acc23);
        acc23 = ffma2(wp[3], q[mid][2], acc23);
        acc23 = ffma2(wp[4], q[mid][3], acc23);
        acc23 = ffma2(wp[5], q[mid][4], acc23);
        acc23 = ffma2(wp[6], q[bot][2], acc23);
        acc23 = ffma2(wp[7], q[bot][3], acc23);
        acc23 = ffma2(wp[8], q[bot][4], acc23);

        // Row stride 510*4 = 2040 B is 8-byte aligned -> STG.64 stores.
        float* orow = o + (size_t)(r0 + r) * 510 + x0;
        *reinterpret_cast<u64*>(orow) = acc01;
        if (!last) {
            *reinterpret_cast<u64*>(orow + 2) = acc23;
        }
    }
}

extern "C" void kernel_launch(void* const* d_in, const int* in_sizes, int n_in,
                              void* d_out, int out_size) {
    const float* x = (const float*)d_in[0];
    const float* w = (const float*)d_in[1];
    // Defensive: metadata order is (x, weight); swap if sizes say otherwise.
    if (n_in >= 2 && in_sizes[0] < in_sizes[1]) {
        const float* t = x; x = w; w = t;
    }
    float* out = (float*)d_out;

    dim3 grid(51, 64, 16); // 510/TILE_H row tiles, C, N
    dwconv3x3_kernel<<<grid, THREADS>>>(x, w, out);
}